// round 16
// baseline (speedup 1.0000x reference)
#include <cuda_runtime.h>
#include <cuda_bf16.h>
#include <math.h>

#define CB 4
#define CT 2048
#define CD 1024
#define CH 8
#define CHD 128
#define CM (CB * CT)
#define YTOT (CM * CD)
#define STOT (CB * CH * CHD * CHD)
#define RES_SCALE 0.5f

#define W_QW 0
#define W_KW (1024 * 1024)
#define W_VW (2 * 1024 * 1024)
#define W_GW (3 * 1024 * 1024)
#define W_OW (4 * 1024 * 1024)
#define W_FCW (5 * 1024 * 1024)
#define W_PW (9 * 1024 * 1024)
#define W_TOT (13 * 1024 * 1024)

__device__ float g_q[CM * CD];
__device__ float g_k[CM * CD];
__device__ float g_v[CM * CD];
__device__ float g_gate[CM * CD];
__device__ float g_o[CM * CD];
__device__ float g_attn[CM * CD];
__device__ float g_x1[CM * CD];
__device__ float g_beta[CM * CH];
__device__ float g_eg[CM * CH];
__device__ float g_sfdummy[STOT];

__device__ __nv_bfloat16 g_hh[CM * CD];
__device__ __nv_bfloat16 g_hl[CM * CD];
__device__ __nv_bfloat16 g_h2h[CM * CD];
__device__ __nv_bfloat16 g_h2l[CM * CD];
__device__ __nv_bfloat16 g_oh[CM * CD];
__device__ __nv_bfloat16 g_ol[CM * CD];
__device__ __nv_bfloat16 g_mlph[CM * 4 * CD];
__device__ __nv_bfloat16 g_mlpl[CM * 4 * CD];
__device__ __nv_bfloat16 g_wth[W_TOT];
__device__ __nv_bfloat16 g_wtl[W_TOT];

__device__ __forceinline__ float siluf(float x) { return x / (1.0f + expf(-x)); }

__device__ __forceinline__ float warpAllSum(float v) {
    v += __shfl_xor_sync(0xffffffffu, v, 16);
    v += __shfl_xor_sync(0xffffffffu, v, 8);
    v += __shfl_xor_sync(0xffffffffu, v, 4);
    v += __shfl_xor_sync(0xffffffffu, v, 2);
    v += __shfl_xor_sync(0xffffffffu, v, 1);
    return v;
}

__device__ __forceinline__ void split_pair(float a, float b,
                                           __nv_bfloat16* hi, __nv_bfloat16* lo) {
    __nv_bfloat16 h0 = __float2bfloat16(a);
    __nv_bfloat16 h1 = __float2bfloat16(b);
    float r0 = a - __bfloat162float(h0);
    float r1 = b - __bfloat162float(h1);
    __nv_bfloat162 hv; hv.x = h0; hv.y = h1;
    __nv_bfloat162 lv; lv.x = __float2bfloat16(r0); lv.y = __float2bfloat16(r1);
    *(__nv_bfloat162*)hi = hv;
    *(__nv_bfloat162*)lo = lv;
}

__device__ __forceinline__ void cpa16(unsigned dst, const void* src) {
    asm volatile("cp.async.ca.shared.global [%0], [%1], 16;" :: "r"(dst), "l"(src));
}
__device__ __forceinline__ void cpa4(unsigned dst, const void* src) {
    asm volatile("cp.async.ca.shared.global [%0], [%1], 4;" :: "r"(dst), "l"(src));
}

__device__ __forceinline__ void mma16816(float* c, const unsigned* a, const unsigned* b) {
    asm volatile(
        "mma.sync.aligned.m16n8k16.row.col.f32.bf16.bf16.f32 "
        "{%0,%1,%2,%3},{%4,%5,%6,%7},{%8,%9},{%0,%1,%2,%3};"
        : "+f"(c[0]), "+f"(c[1]), "+f"(c[2]), "+f"(c[3])
        : "r"(a[0]), "r"(a[1]), "r"(a[2]), "r"(a[3]), "r"(b[0]), "r"(b[1]));
}
__device__ __forceinline__ void ldsm4(unsigned* d, unsigned addr) {
    asm volatile("ldmatrix.sync.aligned.m8n8.x4.shared.b16 {%0,%1,%2,%3}, [%4];"
                 : "=r"(d[0]), "=r"(d[1]), "=r"(d[2]), "=r"(d[3]) : "r"(addr));
}
__device__ __forceinline__ void ldsm2(unsigned* d, unsigned addr) {
    asm volatile("ldmatrix.sync.aligned.m8n8.x2.shared.b16 {%0,%1}, [%2];"
                 : "=r"(d[0]), "=r"(d[1]) : "r"(addr));
}

// -------------------- pipelined tensor-core GEMM --------------------------
// EPI 0: fp32 out. 1: silu -> bf16 hi/lo. 2: silu + per-head l2norm -> fp32.
// 3: silu -> fp32. 4: out = X1 + 0.5*acc -> fp32.
// kh body restructured: load ALL fragments, then 3 passes of 16 independent
// MMAs (same-acc reuse now 16 issues apart -> accumulator RAW fully hidden).
#define SSTRIDE 40
#define GPLANE (128 * SSTRIDE)
#define GSTAGE (4 * GPLANE)
#define GSMEM (2 * GSTAGE * 2)

template <int EPI>
__global__ __launch_bounds__(256, 2) void gemm_tc(
    const __nv_bfloat16* __restrict__ Ahi, const __nv_bfloat16* __restrict__ Alo,
    const __nv_bfloat16* __restrict__ Bhi, const __nv_bfloat16* __restrict__ Blo,
    float* __restrict__ C, __nv_bfloat16* __restrict__ Chi,
    __nv_bfloat16* __restrict__ Clo, const float* __restrict__ X1,
    int M, int N, int K) {
    extern __shared__ __nv_bfloat16 smp[];
    __shared__ float red[128][4];

    int tid = threadIdx.x, warp = tid >> 5, lane = tid & 31;
    int wm = warp >> 2, wn = warp & 3;
    int bm = blockIdx.y * 128, bn = blockIdx.x * 128;
    int lrow = tid >> 1, eoff = (tid & 1) * 16;
    const __nv_bfloat16* pAh = Ahi + (size_t)(bm + lrow) * K + eoff;
    const __nv_bfloat16* pAl = Alo + (size_t)(bm + lrow) * K + eoff;
    const __nv_bfloat16* pBh = Bhi + (size_t)(bn + lrow) * K + eoff;
    const __nv_bfloat16* pBl = Blo + (size_t)(bn + lrow) * K + eoff;
    unsigned sbase = (unsigned)__cvta_generic_to_shared(smp);
    unsigned drow = (unsigned)((lrow * SSTRIDE + eoff) * 2);

    auto issue = [&](int kb, int s) {
        unsigned sb = sbase + (unsigned)(s * (GSTAGE * 2)) + drow;
        cpa16(sb + 0 * (GPLANE * 2), pAh + kb);
        cpa16(sb + 0 * (GPLANE * 2) + 16, pAh + kb + 8);
        cpa16(sb + 1 * (GPLANE * 2), pAl + kb);
        cpa16(sb + 1 * (GPLANE * 2) + 16, pAl + kb + 8);
        cpa16(sb + 2 * (GPLANE * 2), pBh + kb);
        cpa16(sb + 2 * (GPLANE * 2) + 16, pBh + kb + 8);
        cpa16(sb + 3 * (GPLANE * 2), pBl + kb);
        cpa16(sb + 3 * (GPLANE * 2) + 16, pBl + kb + 8);
        asm volatile("cp.async.commit_group;" ::: "memory");
    };
    issue(0, 0);
    issue(32, 1);

    float acc[4][4][4];
#pragma unroll
    for (int i = 0; i < 4; i++)
#pragma unroll
        for (int j = 0; j < 4; j++)
#pragma unroll
            for (int p = 0; p < 4; p++) acc[i][j][p] = 0.0f;

    int sub = lane >> 3, r8 = lane & 7;
    unsigned aoffs = (unsigned)(((wm * 64 + (sub & 1) * 8 + r8) * SSTRIDE + (sub >> 1) * 8) * 2);
    int lb = lane & 15;
    unsigned boffs = (unsigned)(((wn * 32 + (lb & 7)) * SSTRIDE + (lb >> 3) * 8) * 2);

    int nkb = K >> 5;
    for (int it = 0; it < nkb; it++) {
        asm volatile("cp.async.wait_group 1;" ::: "memory");
        __syncthreads();
        unsigned sb = sbase + (unsigned)((it & 1) * (GSTAGE * 2));
        unsigned bAh = sb, bAl = sb + GPLANE * 2;
        unsigned bBh = sb + 2 * (GPLANE * 2), bBl = sb + 3 * (GPLANE * 2);
#pragma unroll
        for (int kh = 0; kh < 2; kh++) {
            unsigned bh[4][2], bl[4][2];
            unsigned ah[4][4], al[4][4];
#pragma unroll
            for (int ni = 0; ni < 4; ni++) {
                unsigned bo = boffs + (unsigned)((ni * 8 * SSTRIDE + kh * 16) * 2);
                ldsm2(bh[ni], bBh + bo);
                ldsm2(bl[ni], bBl + bo);
            }
#pragma unroll
            for (int mi = 0; mi < 4; mi++) {
                unsigned ao = aoffs + (unsigned)((mi * 16 * SSTRIDE + kh * 16) * 2);
                ldsm4(ah[mi], bAh + ao);
                ldsm4(al[mi], bAl + ao);
            }
            // pass 1: hh — 16 independent MMAs
#pragma unroll
            for (int mi = 0; mi < 4; mi++)
#pragma unroll
                for (int ni = 0; ni < 4; ni++)
                    mma16816(acc[mi][ni], ah[mi], bh[ni]);
            // pass 2: hl
#pragma unroll
            for (int mi = 0; mi < 4; mi++)
#pragma unroll
                for (int ni = 0; ni < 4; ni++)
                    mma16816(acc[mi][ni], ah[mi], bl[ni]);
            // pass 3: lh
#pragma unroll
            for (int mi = 0; mi < 4; mi++)
#pragma unroll
                for (int ni = 0; ni < 4; ni++)
                    mma16816(acc[mi][ni], al[mi], bh[ni]);
        }
        __syncthreads();
        if (it + 2 < nkb) issue((it + 2) * 32, it & 1);
        else asm volatile("cp.async.commit_group;" ::: "memory");
    }

    int g = lane >> 2;
    int tig = lane & 3;

    if (EPI == 2 || EPI == 3) {
#pragma unroll
        for (int mi = 0; mi < 4; mi++)
#pragma unroll
            for (int ni = 0; ni < 4; ni++)
#pragma unroll
                for (int p = 0; p < 4; p++) acc[mi][ni][p] = siluf(acc[mi][ni][p]);
    }
    if (EPI == 2) {
#pragma unroll
        for (int mi = 0; mi < 4; mi++) {
            float s0 = 0.0f, s1 = 0.0f;
#pragma unroll
            for (int ni = 0; ni < 4; ni++) {
                s0 += acc[mi][ni][0] * acc[mi][ni][0] + acc[mi][ni][1] * acc[mi][ni][1];
                s1 += acc[mi][ni][2] * acc[mi][ni][2] + acc[mi][ni][3] * acc[mi][ni][3];
            }
            s0 += __shfl_xor_sync(0xffffffffu, s0, 1);
            s0 += __shfl_xor_sync(0xffffffffu, s0, 2);
            s1 += __shfl_xor_sync(0xffffffffu, s1, 1);
            s1 += __shfl_xor_sync(0xffffffffu, s1, 2);
            if (tig == 0) {
                red[wm * 64 + mi * 16 + g][wn] = s0;
                red[wm * 64 + mi * 16 + g + 8][wn] = s1;
            }
        }
        __syncthreads();
    }

#pragma unroll
    for (int mi = 0; mi < 4; mi++) {
        float sc0 = 1.0f, sc1 = 1.0f;
        if (EPI == 2) {
            int rl = wm * 64 + mi * 16 + g;
            float t0 = red[rl][0] + red[rl][1] + red[rl][2] + red[rl][3];
            float t1 = red[rl + 8][0] + red[rl + 8][1] + red[rl + 8][2] + red[rl + 8][3];
            sc0 = rsqrtf(t0 + 1e-6f);
            sc1 = rsqrtf(t1 + 1e-6f);
        }
#pragma unroll
        for (int ni = 0; ni < 4; ni++) {
            int row0 = bm + wm * 64 + mi * 16 + g;
            int col = bn + wn * 32 + ni * 8 + tig * 2;
            if (EPI == 1) {
                float s0 = siluf(acc[mi][ni][0]), s1 = siluf(acc[mi][ni][1]);
                float s2 = siluf(acc[mi][ni][2]), s3 = siluf(acc[mi][ni][3]);
                split_pair(s0, s1, &Chi[(size_t)row0 * N + col], &Clo[(size_t)row0 * N + col]);
                split_pair(s2, s3, &Chi[(size_t)(row0 + 8) * N + col], &Clo[(size_t)(row0 + 8) * N + col]);
            } else {
                float2 t0, t1;
                if (EPI == 4) {
                    float2 a0 = *(const float2*)&X1[(size_t)row0 * N + col];
                    float2 a1 = *(const float2*)&X1[(size_t)(row0 + 8) * N + col];
                    t0.x = a0.x + RES_SCALE * acc[mi][ni][0];
                    t0.y = a0.y + RES_SCALE * acc[mi][ni][1];
                    t1.x = a1.x + RES_SCALE * acc[mi][ni][2];
                    t1.y = a1.y + RES_SCALE * acc[mi][ni][3];
                } else if (EPI == 2) {
                    t0.x = acc[mi][ni][0] * sc0; t0.y = acc[mi][ni][1] * sc0;
                    t1.x = acc[mi][ni][2] * sc1; t1.y = acc[mi][ni][3] * sc1;
                } else {
                    t0.x = acc[mi][ni][0]; t0.y = acc[mi][ni][1];
                    t1.x = acc[mi][ni][2]; t1.y = acc[mi][ni][3];
                }
                *(float2*)&C[(size_t)row0 * N + col] = t0;
                *(float2*)&C[(size_t)(row0 + 8) * N + col] = t1;
            }
        }
    }
}

// ---------- fused weight split+transpose --------------------------------
__global__ void wsplit_all(const float* __restrict__ qw, const float* __restrict__ kw,
                           const float* __restrict__ vw, const float* __restrict__ gw,
                           const float* __restrict__ ow, const float* __restrict__ fcw,
                           const float* __restrict__ pw,
                           __nv_bfloat16* __restrict__ hi, __nv_bfloat16* __restrict__ lo) {
    int bid = blockIdx.x;
    const float* W;
    int K, N, t;
    size_t woff;
    if (bid < 5120) {
        int wsel = bid >> 10;
        t = bid & 1023; K = 1024; N = 1024;
        W = (wsel == 0) ? qw : (wsel == 1) ? kw : (wsel == 2) ? vw : (wsel == 3) ? gw : ow;
        woff = (size_t)wsel << 20;
    } else if (bid < 9216) {
        t = bid - 5120; K = 1024; N = 4096; W = fcw; woff = W_FCW;
    } else {
        t = bid - 9216; K = 4096; N = 1024; W = pw; woff = W_PW;
    }
    int ntiles = N >> 5;
    int nb = (t % ntiles) * 32, kb = (t / ntiles) * 32;
    __shared__ float tile[32][33];
    int tx = threadIdx.x & 31, ty = threadIdx.x >> 5;
#pragma unroll
    for (int i = 0; i < 32; i += 8)
        tile[ty + i][tx] = W[(size_t)(kb + ty + i) * N + nb + tx];
    __syncthreads();
#pragma unroll
    for (int i = 0; i < 32; i += 8) {
        float x = tile[tx][ty + i];
        size_t oidx = woff + (size_t)(nb + ty + i) * K + kb + tx;
        __nv_bfloat16 h = __float2bfloat16(x);
        hi[oidx] = h;
        lo[oidx] = __float2bfloat16(x - __bfloat162float(h));
    }
}

// ---- fused rmsnorm + beta/eg projections ---------------------------------
__global__ void rmsnorm_bg_k(const float* __restrict__ x, const float* __restrict__ w,
                             const float* __restrict__ bw, const float* __restrict__ aw,
                             const float* __restrict__ A_log, const float* __restrict__ dt_bias,
                             __nv_bfloat16* __restrict__ ohi, __nv_bfloat16* __restrict__ olo,
                             float* __restrict__ beta, float* __restrict__ eg) {
    int row = blockIdx.x, tid = threadIdx.x;
    float4 v = ((const float4*)(x + (size_t)row * CD))[tid];
    float ss = v.x * v.x + v.y * v.y + v.z * v.z + v.w * v.w;
    __shared__ float red[8];
    __shared__ float red2[8][16];
    int lane = tid & 31, warp = tid >> 5;
    ss = warpAllSum(ss);
    if (lane == 0) red[warp] = ss;
    __syncthreads();
    float tot = red[0] + red[1] + red[2] + red[3] + red[4] + red[5] + red[6] + red[7];
    float sc = rsqrtf(tot * (1.0f / CD) + 1e-6f);
    float4 wv = ((const float4*)w)[tid];
    float4 o;
    o.x = v.x * wv.x * sc; o.y = v.y * wv.y * sc;
    o.z = v.z * wv.z * sc; o.w = v.w * wv.w * sc;
    size_t e = (size_t)row * CD + tid * 4;
    split_pair(o.x, o.y, ohi + e, olo + e);
    split_pair(o.z, o.w, ohi + e + 2, olo + e + 2);

    float hx[4] = {o.x, o.y, o.z, o.w};
    float aB[8], aA[8];
#pragma unroll
    for (int j = 0; j < 8; j++) { aB[j] = 0.0f; aA[j] = 0.0f; }
#pragma unroll
    for (int i = 0; i < 4; i++) {
        int kk = tid * 4 + i;
        float xv = hx[i];
        float4 b0 = ((const float4*)(bw + (size_t)kk * CH))[0];
        float4 b1 = ((const float4*)(bw + (size_t)kk * CH))[1];
        float4 a0 = ((const float4*)(aw + (size_t)kk * CH))[0];
        float4 a1 = ((const float4*)(aw + (size_t)kk * CH))[1];
        aB[0] = fmaf(xv, b0.x, aB[0]); aB[1] = fmaf(xv, b0.y, aB[1]);
        aB[2] = fmaf(xv, b0.z, aB[2]); aB[3] = fmaf(xv, b0.w, aB[3]);
        aB[4] = fmaf(xv, b1.x, aB[4]); aB[5] = fmaf(xv, b1.y, aB[5]);
        aB[6] = fmaf(xv, b1.z, aB[6]); aB[7] = fmaf(xv, b1.w, aB[7]);
        aA[0] = fmaf(xv, a0.x, aA[0]); aA[1] = fmaf(xv, a0.y, aA[1]);
        aA[2] = fmaf(xv, a0.z, aA[2]); aA[3] = fmaf(xv, a0.w, aA[3]);
        aA[4] = fmaf(xv, a1.x, aA[4]); aA[5] = fmaf(xv, a1.y, aA[5]);
        aA[6] = fmaf(xv, a1.z, aA[6]); aA[7] = fmaf(xv, a1.w, aA[7]);
    }
#pragma unroll
    for (int j = 0; j < 8; j++) { aB[j] = warpAllSum(aB[j]); aA[j] = warpAllSum(aA[j]); }
    if (lane == 0) {
#pragma unroll
        for (int j = 0; j < 8; j++) { red2[warp][j] = aB[j]; red2[warp][j + 8] = aA[j]; }
    }
    __syncthreads();
    if (tid < 16) {
        float s = 0.0f;
#pragma unroll
        for (int w8 = 0; w8 < 8; w8++) s += red2[w8][tid];
        if (tid < 8) {
            beta[(size_t)row * CH + tid] = 1.0f / (1.0f + expf(-s));
        } else {
            int j = tid - 8;
            float z = s + dt_bias[j];
            float sp = (z > 20.0f) ? z : log1pf(expf(z));
            float gg = -expf(A_log[j]) * sp;
            eg[(size_t)row * CH + j] = expf(gg);
        }
    }
}

// -------------------- elementwise kernels --------------------------------
__global__ void resid_rms_k(const float* __restrict__ x, const float* __restrict__ a,
                            const float* __restrict__ w, float* __restrict__ x1,
                            __nv_bfloat16* __restrict__ h2h, __nv_bfloat16* __restrict__ h2l) {
    int row = blockIdx.x, tid = threadIdx.x;
    float4 xv = ((const float4*)(x + (size_t)row * CD))[tid];
    float4 av = ((const float4*)(a + (size_t)row * CD))[tid];
    float4 v;
    v.x = xv.x + RES_SCALE * av.x; v.y = xv.y + RES_SCALE * av.y;
    v.z = xv.z + RES_SCALE * av.z; v.w = xv.w + RES_SCALE * av.w;
    ((float4*)(x1 + (size_t)row * CD))[tid] = v;
    float ss = v.x * v.x + v.y * v.y + v.z * v.z + v.w * v.w;
    __shared__ float red[8];
    int lane = tid & 31, warp = tid >> 5;
    ss = warpAllSum(ss);
    if (lane == 0) red[warp] = ss;
    __syncthreads();
    float tot = red[0] + red[1] + red[2] + red[3] + red[4] + red[5] + red[6] + red[7];
    float sc = rsqrtf(tot * (1.0f / CD) + 1e-6f);
    float4 wv = ((const float4*)w)[tid];
    float4 o;
    o.x = v.x * wv.x * sc; o.y = v.y * wv.y * sc;
    o.z = v.z * wv.z * sc; o.w = v.w * wv.w * sc;
    size_t e = (size_t)row * CD + tid * 4;
    split_pair(o.x, o.y, h2h + e, h2l + e);
    split_pair(o.z, o.w, h2h + e + 2, h2l + e + 2);
}

__global__ void onorm_gate_k(const float* __restrict__ o, const float* __restrict__ gate,
                             const float* __restrict__ onw,
                             __nv_bfloat16* __restrict__ oh, __nv_bfloat16* __restrict__ ol) {
    int row = blockIdx.x;
    int lane = threadIdx.x & 31, warp = threadIdx.x >> 5;
    size_t base4 = (size_t)row * (CD / 4) + warp * (CHD / 4) + lane;
    float4 ov = ((const float4*)o)[base4];
    float ss = warpAllSum(ov.x * ov.x + ov.y * ov.y + ov.z * ov.z + ov.w * ov.w);
    float sc = rsqrtf(ss * (1.0f / CHD) + 1e-6f);
    float4 gv = ((const float4*)gate)[base4];
    gv.x = siluf(gv.x); gv.y = siluf(gv.y); gv.z = siluf(gv.z); gv.w = siluf(gv.w);
    float4 wv = ((const float4*)onw)[lane];
    float4 r;
    r.x = ov.x * sc * wv.x * gv.x;
    r.y = ov.y * sc * wv.y * gv.y;
    r.z = ov.z * sc * wv.z * gv.z;
    r.w = ov.w * sc * wv.w * gv.w;
    size_t e = base4 * 4;
    split_pair(r.x, r.y, oh + e, ol + e);
    split_pair(r.z, r.w, oh + e + 2, ol + e + 2);
}

// ------- gated delta-rule scan: depth-8 pipeline, 1 barrier/step ----------
#define SC_ST 8
#define SROW 144
__global__ __launch_bounds__(128) void scan_k(
    const float* __restrict__ q, const float* __restrict__ k,
    const float* __restrict__ v, const float* __restrict__ beta,
    const float* __restrict__ eg, float* __restrict__ o, float* __restrict__ sf) {
    __shared__ float sk[SC_ST][SROW];
    __shared__ float sq[SC_ST][SROW];
    __shared__ float sv[SC_ST][40];

    int bh = blockIdx.x >> 2, quar = blockIdx.x & 3;
    int b = bh >> 3, hh = bh & 7;
    int tid = threadIdx.x;
    int warp = tid >> 5, lane = tid & 31;
    int colL = lane >> 2;
    int col = quar * 32 + warp * 8 + colL;
    int seg = lane & 3;
    int vbase = quar * 32;

    unsigned skb = (unsigned)__cvta_generic_to_shared(sk);
    unsigned sqb = (unsigned)__cvta_generic_to_shared(sq);
    unsigned svb = (unsigned)__cvta_generic_to_shared(sv);

    int rowbase = b * CT * CH + hh;

    auto issue = [&](int t) {
        if (t < CT) {
            int idx = rowbase + t * CH;
            int st = t & (SC_ST - 1);
            if (tid < 32) {
                int d = tid * 4;
                unsigned pos = (unsigned)((st * SROW + (d >> 5) * 36 + (d & 31)) * 4);
                cpa16(skb + pos, k + (size_t)idx * CHD + d);
            } else if (tid < 64) {
                int d = (tid - 32) * 4;
                unsigned pos = (unsigned)((st * SROW + (d >> 5) * 36 + (d & 31)) * 4);
                cpa16(sqb + pos, q + (size_t)idx * CHD + d);
            } else if (tid < 72) {
                int d = (tid - 64) * 4;
                cpa16(svb + (unsigned)((st * 40 + d) * 4), v + (size_t)idx * CHD + vbase + d);
            } else if (tid == 72) {
                cpa4(svb + (unsigned)((st * 40 + 32) * 4), eg + idx);
            } else if (tid == 73) {
                cpa4(svb + (unsigned)((st * 40 + 33) * 4), beta + idx);
            }
        }
        asm volatile("cp.async.commit_group;" ::: "memory");
    };

#pragma unroll
    for (int t = 0; t < SC_ST - 1; t++) issue(t);

    float S[32];
#pragma unroll
    for (int j = 0; j < 32; j++) S[j] = 0.0f;

    for (int t = 0; t < CT; t++) {
        int st = t & (SC_ST - 1);
        asm volatile("cp.async.wait_group 6;" ::: "memory");
        __syncthreads();
        issue(t + SC_ST - 1);
        const float* kp = &sk[st][seg * 36];
        const float* qp = &sq[st][seg * 36];
        float egv = sv[st][32];
        float btv = sv[st][33];
        float vtv = sv[st][warp * 8 + colL];

        float kr[32];
        float kS0 = 0.0f, kS1 = 0.0f, kS2 = 0.0f, kS3 = 0.0f;
#pragma unroll
        for (int j = 0; j < 32; j += 4) {
            float k0 = kp[j], k1 = kp[j + 1], k2 = kp[j + 2], k3 = kp[j + 3];
            kr[j] = k0; kr[j + 1] = k1; kr[j + 2] = k2; kr[j + 3] = k3;
            float s0 = S[j] * egv, s1 = S[j + 1] * egv;
            float s2 = S[j + 2] * egv, s3 = S[j + 3] * egv;
            S[j] = s0; S[j + 1] = s1; S[j + 2] = s2; S[j + 3] = s3;
            kS0 = fmaf(k0, s0, kS0); kS1 = fmaf(k1, s1, kS1);
            kS2 = fmaf(k2, s2, kS2); kS3 = fmaf(k3, s3, kS3);
        }
        float kS = (kS0 + kS1) + (kS2 + kS3);
        kS += __shfl_xor_sync(0xffffffffu, kS, 1);
        kS += __shfl_xor_sync(0xffffffffu, kS, 2);
        float bd = btv * (vtv - kS);

        float o0 = 0.0f, o1 = 0.0f, o2 = 0.0f, o3 = 0.0f;
#pragma unroll
        for (int j = 0; j < 32; j += 4) {
            float s0 = fmaf(kr[j], bd, S[j]);
            float s1 = fmaf(kr[j + 1], bd, S[j + 1]);
            float s2 = fmaf(kr[j + 2], bd, S[j + 2]);
            float s3 = fmaf(kr[j + 3], bd, S[j + 3]);
            S[j] = s0; S[j + 1] = s1; S[j + 2] = s2; S[j + 3] = s3;
            o0 = fmaf(qp[j], s0, o0); o1 = fmaf(qp[j + 1], s1, o1);
            o2 = fmaf(qp[j + 2], s2, o2); o3 = fmaf(qp[j + 3], s3, o3);
        }
        float ot = (o0 + o1) + (o2 + o3);
        ot += __shfl_xor_sync(0xffffffffu, ot, 1);
        ot += __shfl_xor_sync(0xffffffffu, ot, 2);
        if (seg == 0) o[(size_t)(rowbase + t * CH) * CHD + col] = ot;
    }

    float* sfp = sf + ((size_t)bh * CHD + seg * 32) * CHD + col;
#pragma unroll
    for (int j = 0; j < 32; j++) sfp[(size_t)j * CHD] = S[j];
}

// -------------------- launcher --------------------------------------------
static float* symaddrf(const void* sym) {
    void* p = nullptr;
    cudaGetSymbolAddress(&p, sym);
    return (float*)p;
}
static __nv_bfloat16* symaddrb(const void* sym) {
    void* p = nullptr;
    cudaGetSymbolAddress(&p, sym);
    return (__nv_bfloat16*)p;
}

extern "C" void kernel_launch(void* const* d_in, const int* in_sizes, int n_in,
                              void* d_out, int out_size) {
    const float* x       = (const float*)d_in[0];
    const float* ln1_w   = (const float*)d_in[1];
    const float* qw      = (const float*)d_in[2];
    const float* kw      = (const float*)d_in[3];
    const float* vw      = (const float*)d_in[4];
    const float* bw      = (const float*)d_in[5];
    const float* aw      = (const float*)d_in[6];
    const float* A_log   = (const float*)d_in[7];
    const float* dt_bias = (const float*)d_in[8];
    const float* gw      = (const float*)d_in[9];
    const float* onorm_w = (const float*)d_in[10];
    const float* ow      = (const float*)d_in[11];
    const float* ln2_w   = (const float*)d_in[12];
    const float* fcw     = (const float*)d_in[13];
    const float* pw      = (const float*)d_in[14];
    float* y = (float*)d_out;

    float* q_    = symaddrf(g_q);
    float* k_    = symaddrf(g_k);
    float* v_    = symaddrf(g_v);
    float* gate_ = symaddrf(g_gate);
    float* o_    = symaddrf(g_o);
    float* attn_ = symaddrf(g_attn);
    float* x1_   = symaddrf(g_x1);
    float* beta_ = symaddrf(g_beta);
    float* eg_   = symaddrf(g_eg);
    float* sfd_  = symaddrf(g_sfdummy);

    __nv_bfloat16* hh_   = symaddrb(g_hh);
    __nv_bfloat16* hl_   = symaddrb(g_hl);
    __nv_bfloat16* h2h_  = symaddrb(g_h2h);
    __nv_bfloat16* h2l_  = symaddrb(g_h2l);
    __nv_bfloat16* oh_   = symaddrb(g_oh);
    __nv_bfloat16* ol_   = symaddrb(g_ol);
    __nv_bfloat16* mlph_ = symaddrb(g_mlph);
    __nv_bfloat16* mlpl_ = symaddrb(g_mlpl);
    __nv_bfloat16* wth_  = symaddrb(g_wth);
    __nv_bfloat16* wtl_  = symaddrb(g_wtl);

    float* sfdst = (out_size >= YTOT + STOT) ? (y + YTOT) : sfd_;

    static int smem_set = 0;
    if (!smem_set) {
        cudaFuncSetAttribute(gemm_tc<0>, cudaFuncAttributeMaxDynamicSharedMemorySize, GSMEM);
        cudaFuncSetAttribute(gemm_tc<1>, cudaFuncAttributeMaxDynamicSharedMemorySize, GSMEM);
        cudaFuncSetAttribute(gemm_tc<2>, cudaFuncAttributeMaxDynamicSharedMemorySize, GSMEM);
        cudaFuncSetAttribute(gemm_tc<3>, cudaFuncAttributeMaxDynamicSharedMemorySize, GSMEM);
        cudaFuncSetAttribute(gemm_tc<4>, cudaFuncAttributeMaxDynamicSharedMemorySize, GSMEM);
        smem_set = 1;
    }

    dim3 blk(256);
    dim3 g1024(1024 / 128, CM / 128);
    dim3 g4096(4096 / 128, CM / 128);

    rmsnorm_bg_k<<<CM, blk>>>(x, ln1_w, bw, aw, A_log, dt_bias, hh_, hl_, beta_, eg_);
    wsplit_all<<<13312, blk>>>(qw, kw, vw, gw, ow, fcw, pw, wth_, wtl_);
    gemm_tc<2><<<g1024, blk, GSMEM>>>(hh_, hl_, wth_ + W_QW, wtl_ + W_QW, q_, nullptr, nullptr, nullptr, CM, CD, CD);
    gemm_tc<2><<<g1024, blk, GSMEM>>>(hh_, hl_, wth_ + W_KW, wtl_ + W_KW, k_, nullptr, nullptr, nullptr, CM, CD, CD);
    gemm_tc<3><<<g1024, blk, GSMEM>>>(hh_, hl_, wth_ + W_VW, wtl_ + W_VW, v_, nullptr, nullptr, nullptr, CM, CD, CD);
    gemm_tc<0><<<g1024, blk, GSMEM>>>(hh_, hl_, wth_ + W_GW, wtl_ + W_GW, gate_, nullptr, nullptr, nullptr, CM, CD, CD);

    scan_k<<<128, 128>>>(q_, k_, v_, beta_, eg_, o_, sfdst);

    onorm_gate_k<<<CM, blk>>>(o_, gate_, onorm_w, oh_, ol_);
    gemm_tc<0><<<g1024, blk, GSMEM>>>(oh_, ol_, wth_ + W_OW, wtl_ + W_OW, attn_, nullptr, nullptr, nullptr, CM, CD, CD);
    resid_rms_k<<<CM, blk>>>(x, attn_, ln2_w, x1_, h2h_, h2l_);

    gemm_tc<1><<<g4096, blk, GSMEM>>>(h2h_, h2l_, wth_ + W_FCW, wtl_ + W_FCW, nullptr, mlph_, mlpl_, nullptr, CM, 4 * CD, CD);
    gemm_tc<4><<<g1024, blk, GSMEM>>>(mlph_, mlpl_, wth_ + W_PW, wtl_ + W_PW, y, nullptr, nullptr, x1_, CM, CD, 4 * CD);
}

// round 17
// speedup vs baseline: 1.0375x; 1.0375x over previous
#include <cuda_runtime.h>
#include <cuda_bf16.h>
#include <math.h>

#define CB 4
#define CT 2048
#define CD 1024
#define CH 8
#define CHD 128
#define CM (CB * CT)
#define YTOT (CM * CD)
#define STOT (CB * CH * CHD * CHD)
#define RES_SCALE 0.5f

#define W_QW 0
#define W_KW (1024 * 1024)
#define W_VW (2 * 1024 * 1024)
#define W_GW (3 * 1024 * 1024)
#define W_OW (4 * 1024 * 1024)
#define W_FCW (5 * 1024 * 1024)
#define W_PW (9 * 1024 * 1024)
#define W_TOT (13 * 1024 * 1024)

__device__ float g_q[CM * CD];
__device__ float g_k[CM * CD];
__device__ float g_v[CM * CD];
__device__ float g_gate[CM * CD];
__device__ float g_o[CM * CD];
__device__ float g_attn[CM * CD];
__device__ float g_x1[CM * CD];
__device__ float g_beta[CM * CH];
__device__ float g_eg[CM * CH];
__device__ float g_sfdummy[STOT];

__device__ __nv_bfloat16 g_hh[CM * CD];
__device__ __nv_bfloat16 g_hl[CM * CD];
__device__ __nv_bfloat16 g_h2h[CM * CD];
__device__ __nv_bfloat16 g_h2l[CM * CD];
__device__ __nv_bfloat16 g_oh[CM * CD];
__device__ __nv_bfloat16 g_ol[CM * CD];
__device__ __nv_bfloat16 g_mlph[CM * 4 * CD];
__device__ __nv_bfloat16 g_mlpl[CM * 4 * CD];
__device__ __nv_bfloat16 g_wth[W_TOT];
__device__ __nv_bfloat16 g_wtl[W_TOT];

__device__ __forceinline__ float siluf(float x) { return x / (1.0f + expf(-x)); }

__device__ __forceinline__ float warpAllSum(float v) {
    v += __shfl_xor_sync(0xffffffffu, v, 16);
    v += __shfl_xor_sync(0xffffffffu, v, 8);
    v += __shfl_xor_sync(0xffffffffu, v, 4);
    v += __shfl_xor_sync(0xffffffffu, v, 2);
    v += __shfl_xor_sync(0xffffffffu, v, 1);
    return v;
}

__device__ __forceinline__ void split_pair(float a, float b,
                                           __nv_bfloat16* hi, __nv_bfloat16* lo) {
    __nv_bfloat16 h0 = __float2bfloat16(a);
    __nv_bfloat16 h1 = __float2bfloat16(b);
    float r0 = a - __bfloat162float(h0);
    float r1 = b - __bfloat162float(h1);
    __nv_bfloat162 hv; hv.x = h0; hv.y = h1;
    __nv_bfloat162 lv; lv.x = __float2bfloat16(r0); lv.y = __float2bfloat16(r1);
    *(__nv_bfloat162*)hi = hv;
    *(__nv_bfloat162*)lo = lv;
}

__device__ __forceinline__ void cpa16(unsigned dst, const void* src) {
    asm volatile("cp.async.ca.shared.global [%0], [%1], 16;" :: "r"(dst), "l"(src));
}
__device__ __forceinline__ void cpa4(unsigned dst, const void* src) {
    asm volatile("cp.async.ca.shared.global [%0], [%1], 4;" :: "r"(dst), "l"(src));
}

__device__ __forceinline__ void mma16816(float* c, const unsigned* a, const unsigned* b) {
    asm volatile(
        "mma.sync.aligned.m16n8k16.row.col.f32.bf16.bf16.f32 "
        "{%0,%1,%2,%3},{%4,%5,%6,%7},{%8,%9},{%0,%1,%2,%3};"
        : "+f"(c[0]), "+f"(c[1]), "+f"(c[2]), "+f"(c[3])
        : "r"(a[0]), "r"(a[1]), "r"(a[2]), "r"(a[3]), "r"(b[0]), "r"(b[1]));
}
__device__ __forceinline__ void ldsm4(unsigned* d, unsigned addr) {
    asm volatile("ldmatrix.sync.aligned.m8n8.x4.shared.b16 {%0,%1,%2,%3}, [%4];"
                 : "=r"(d[0]), "=r"(d[1]), "=r"(d[2]), "=r"(d[3]) : "r"(addr));
}
__device__ __forceinline__ void ldsm2(unsigned* d, unsigned addr) {
    asm volatile("ldmatrix.sync.aligned.m8n8.x2.shared.b16 {%0,%1}, [%2];"
                 : "=r"(d[0]), "=r"(d[1]) : "r"(addr));
}

// -------------------- pipelined tensor-core GEMM --------------------------
#define SSTRIDE 40
#define GPLANE (128 * SSTRIDE)
#define GSTAGE (4 * GPLANE)
#define GSMEM (2 * GSTAGE * 2)

template <int EPI>
__global__ __launch_bounds__(256, 2) void gemm_tc(
    const __nv_bfloat16* __restrict__ Ahi, const __nv_bfloat16* __restrict__ Alo,
    const __nv_bfloat16* __restrict__ Bhi, const __nv_bfloat16* __restrict__ Blo,
    float* __restrict__ C, __nv_bfloat16* __restrict__ Chi,
    __nv_bfloat16* __restrict__ Clo, const float* __restrict__ X1,
    int M, int N, int K) {
    extern __shared__ __nv_bfloat16 smp[];
    __shared__ float red[128][4];

    int tid = threadIdx.x, warp = tid >> 5, lane = tid & 31;
    int wm = warp >> 2, wn = warp & 3;
    int bm = blockIdx.y * 128, bn = blockIdx.x * 128;
    int lrow = tid >> 1, eoff = (tid & 1) * 16;
    const __nv_bfloat16* pAh = Ahi + (size_t)(bm + lrow) * K + eoff;
    const __nv_bfloat16* pAl = Alo + (size_t)(bm + lrow) * K + eoff;
    const __nv_bfloat16* pBh = Bhi + (size_t)(bn + lrow) * K + eoff;
    const __nv_bfloat16* pBl = Blo + (size_t)(bn + lrow) * K + eoff;
    unsigned sbase = (unsigned)__cvta_generic_to_shared(smp);
    unsigned drow = (unsigned)((lrow * SSTRIDE + eoff) * 2);

    auto issue = [&](int kb, int s) {
        unsigned sb = sbase + (unsigned)(s * (GSTAGE * 2)) + drow;
        cpa16(sb + 0 * (GPLANE * 2), pAh + kb);
        cpa16(sb + 0 * (GPLANE * 2) + 16, pAh + kb + 8);
        cpa16(sb + 1 * (GPLANE * 2), pAl + kb);
        cpa16(sb + 1 * (GPLANE * 2) + 16, pAl + kb + 8);
        cpa16(sb + 2 * (GPLANE * 2), pBh + kb);
        cpa16(sb + 2 * (GPLANE * 2) + 16, pBh + kb + 8);
        cpa16(sb + 3 * (GPLANE * 2), pBl + kb);
        cpa16(sb + 3 * (GPLANE * 2) + 16, pBl + kb + 8);
        asm volatile("cp.async.commit_group;" ::: "memory");
    };
    issue(0, 0);
    issue(32, 1);

    float acc[4][4][4];
#pragma unroll
    for (int i = 0; i < 4; i++)
#pragma unroll
        for (int j = 0; j < 4; j++)
#pragma unroll
            for (int p = 0; p < 4; p++) acc[i][j][p] = 0.0f;

    int sub = lane >> 3, r8 = lane & 7;
    unsigned aoffs = (unsigned)(((wm * 64 + (sub & 1) * 8 + r8) * SSTRIDE + (sub >> 1) * 8) * 2);
    int lb = lane & 15;
    unsigned boffs = (unsigned)(((wn * 32 + (lb & 7)) * SSTRIDE + (lb >> 3) * 8) * 2);

    int nkb = K >> 5;
    for (int it = 0; it < nkb; it++) {
        asm volatile("cp.async.wait_group 1;" ::: "memory");
        __syncthreads();
        unsigned sb = sbase + (unsigned)((it & 1) * (GSTAGE * 2));
        unsigned bAh = sb, bAl = sb + GPLANE * 2;
        unsigned bBh = sb + 2 * (GPLANE * 2), bBl = sb + 3 * (GPLANE * 2);
#pragma unroll
        for (int kh = 0; kh < 2; kh++) {
            unsigned bh[4][2], bl[4][2];
            unsigned ah[4][4], al[4][4];
#pragma unroll
            for (int ni = 0; ni < 4; ni++) {
                unsigned bo = boffs + (unsigned)((ni * 8 * SSTRIDE + kh * 16) * 2);
                ldsm2(bh[ni], bBh + bo);
                ldsm2(bl[ni], bBl + bo);
            }
#pragma unroll
            for (int mi = 0; mi < 4; mi++) {
                unsigned ao = aoffs + (unsigned)((mi * 16 * SSTRIDE + kh * 16) * 2);
                ldsm4(ah[mi], bAh + ao);
                ldsm4(al[mi], bAl + ao);
            }
#pragma unroll
            for (int mi = 0; mi < 4; mi++)
#pragma unroll
                for (int ni = 0; ni < 4; ni++)
                    mma16816(acc[mi][ni], ah[mi], bh[ni]);
#pragma unroll
            for (int mi = 0; mi < 4; mi++)
#pragma unroll
                for (int ni = 0; ni < 4; ni++)
                    mma16816(acc[mi][ni], ah[mi], bl[ni]);
#pragma unroll
            for (int mi = 0; mi < 4; mi++)
#pragma unroll
                for (int ni = 0; ni < 4; ni++)
                    mma16816(acc[mi][ni], al[mi], bh[ni]);
        }
        __syncthreads();
        if (it + 2 < nkb) issue((it + 2) * 32, it & 1);
        else asm volatile("cp.async.commit_group;" ::: "memory");
    }

    int g = lane >> 2;
    int tig = lane & 3;

    if (EPI == 2 || EPI == 3) {
#pragma unroll
        for (int mi = 0; mi < 4; mi++)
#pragma unroll
            for (int ni = 0; ni < 4; ni++)
#pragma unroll
                for (int p = 0; p < 4; p++) acc[mi][ni][p] = siluf(acc[mi][ni][p]);
    }
    if (EPI == 2) {
#pragma unroll
        for (int mi = 0; mi < 4; mi++) {
            float s0 = 0.0f, s1 = 0.0f;
#pragma unroll
            for (int ni = 0; ni < 4; ni++) {
                s0 += acc[mi][ni][0] * acc[mi][ni][0] + acc[mi][ni][1] * acc[mi][ni][1];
                s1 += acc[mi][ni][2] * acc[mi][ni][2] + acc[mi][ni][3] * acc[mi][ni][3];
            }
            s0 += __shfl_xor_sync(0xffffffffu, s0, 1);
            s0 += __shfl_xor_sync(0xffffffffu, s0, 2);
            s1 += __shfl_xor_sync(0xffffffffu, s1, 1);
            s1 += __shfl_xor_sync(0xffffffffu, s1, 2);
            if (tig == 0) {
                red[wm * 64 + mi * 16 + g][wn] = s0;
                red[wm * 64 + mi * 16 + g + 8][wn] = s1;
            }
        }
        __syncthreads();
    }

#pragma unroll
    for (int mi = 0; mi < 4; mi++) {
        float sc0 = 1.0f, sc1 = 1.0f;
        if (EPI == 2) {
            int rl = wm * 64 + mi * 16 + g;
            float t0 = red[rl][0] + red[rl][1] + red[rl][2] + red[rl][3];
            float t1 = red[rl + 8][0] + red[rl + 8][1] + red[rl + 8][2] + red[rl + 8][3];
            sc0 = rsqrtf(t0 + 1e-6f);
            sc1 = rsqrtf(t1 + 1e-6f);
        }
#pragma unroll
        for (int ni = 0; ni < 4; ni++) {
            int row0 = bm + wm * 64 + mi * 16 + g;
            int col = bn + wn * 32 + ni * 8 + tig * 2;
            if (EPI == 1) {
                float s0 = siluf(acc[mi][ni][0]), s1 = siluf(acc[mi][ni][1]);
                float s2 = siluf(acc[mi][ni][2]), s3 = siluf(acc[mi][ni][3]);
                split_pair(s0, s1, &Chi[(size_t)row0 * N + col], &Clo[(size_t)row0 * N + col]);
                split_pair(s2, s3, &Chi[(size_t)(row0 + 8) * N + col], &Clo[(size_t)(row0 + 8) * N + col]);
            } else {
                float2 t0, t1;
                if (EPI == 4) {
                    float2 a0 = *(const float2*)&X1[(size_t)row0 * N + col];
                    float2 a1 = *(const float2*)&X1[(size_t)(row0 + 8) * N + col];
                    t0.x = a0.x + RES_SCALE * acc[mi][ni][0];
                    t0.y = a0.y + RES_SCALE * acc[mi][ni][1];
                    t1.x = a1.x + RES_SCALE * acc[mi][ni][2];
                    t1.y = a1.y + RES_SCALE * acc[mi][ni][3];
                } else if (EPI == 2) {
                    t0.x = acc[mi][ni][0] * sc0; t0.y = acc[mi][ni][1] * sc0;
                    t1.x = acc[mi][ni][2] * sc1; t1.y = acc[mi][ni][3] * sc1;
                } else {
                    t0.x = acc[mi][ni][0]; t0.y = acc[mi][ni][1];
                    t1.x = acc[mi][ni][2]; t1.y = acc[mi][ni][3];
                }
                *(float2*)&C[(size_t)row0 * N + col] = t0;
                *(float2*)&C[(size_t)(row0 + 8) * N + col] = t1;
            }
        }
    }
}

// ---------- fused weight split+transpose --------------------------------
__global__ void wsplit_all(const float* __restrict__ qw, const float* __restrict__ kw,
                           const float* __restrict__ vw, const float* __restrict__ gw,
                           const float* __restrict__ ow, const float* __restrict__ fcw,
                           const float* __restrict__ pw,
                           __nv_bfloat16* __restrict__ hi, __nv_bfloat16* __restrict__ lo) {
    int bid = blockIdx.x;
    const float* W;
    int K, N, t;
    size_t woff;
    if (bid < 5120) {
        int wsel = bid >> 10;
        t = bid & 1023; K = 1024; N = 1024;
        W = (wsel == 0) ? qw : (wsel == 1) ? kw : (wsel == 2) ? vw : (wsel == 3) ? gw : ow;
        woff = (size_t)wsel << 20;
    } else if (bid < 9216) {
        t = bid - 5120; K = 1024; N = 4096; W = fcw; woff = W_FCW;
    } else {
        t = bid - 9216; K = 4096; N = 1024; W = pw; woff = W_PW;
    }
    int ntiles = N >> 5;
    int nb = (t % ntiles) * 32, kb = (t / ntiles) * 32;
    __shared__ float tile[32][33];
    int tx = threadIdx.x & 31, ty = threadIdx.x >> 5;
#pragma unroll
    for (int i = 0; i < 32; i += 8)
        tile[ty + i][tx] = W[(size_t)(kb + ty + i) * N + nb + tx];
    __syncthreads();
#pragma unroll
    for (int i = 0; i < 32; i += 8) {
        float x = tile[tx][ty + i];
        size_t oidx = woff + (size_t)(nb + ty + i) * K + kb + tx;
        __nv_bfloat16 h = __float2bfloat16(x);
        hi[oidx] = h;
        lo[oidx] = __float2bfloat16(x - __bfloat162float(h));
    }
}

// ---- fused rmsnorm + beta/eg projections ---------------------------------
__global__ void rmsnorm_bg_k(const float* __restrict__ x, const float* __restrict__ w,
                             const float* __restrict__ bw, const float* __restrict__ aw,
                             const float* __restrict__ A_log, const float* __restrict__ dt_bias,
                             __nv_bfloat16* __restrict__ ohi, __nv_bfloat16* __restrict__ olo,
                             float* __restrict__ beta, float* __restrict__ eg) {
    int row = blockIdx.x, tid = threadIdx.x;
    float4 v = ((const float4*)(x + (size_t)row * CD))[tid];
    float ss = v.x * v.x + v.y * v.y + v.z * v.z + v.w * v.w;
    __shared__ float red[8];
    __shared__ float red2[8][16];
    int lane = tid & 31, warp = tid >> 5;
    ss = warpAllSum(ss);
    if (lane == 0) red[warp] = ss;
    __syncthreads();
    float tot = red[0] + red[1] + red[2] + red[3] + red[4] + red[5] + red[6] + red[7];
    float sc = rsqrtf(tot * (1.0f / CD) + 1e-6f);
    float4 wv = ((const float4*)w)[tid];
    float4 o;
    o.x = v.x * wv.x * sc; o.y = v.y * wv.y * sc;
    o.z = v.z * wv.z * sc; o.w = v.w * wv.w * sc;
    size_t e = (size_t)row * CD + tid * 4;
    split_pair(o.x, o.y, ohi + e, olo + e);
    split_pair(o.z, o.w, ohi + e + 2, olo + e + 2);

    float hx[4] = {o.x, o.y, o.z, o.w};
    float aB[8], aA[8];
#pragma unroll
    for (int j = 0; j < 8; j++) { aB[j] = 0.0f; aA[j] = 0.0f; }
#pragma unroll
    for (int i = 0; i < 4; i++) {
        int kk = tid * 4 + i;
        float xv = hx[i];
        float4 b0 = ((const float4*)(bw + (size_t)kk * CH))[0];
        float4 b1 = ((const float4*)(bw + (size_t)kk * CH))[1];
        float4 a0 = ((const float4*)(aw + (size_t)kk * CH))[0];
        float4 a1 = ((const float4*)(aw + (size_t)kk * CH))[1];
        aB[0] = fmaf(xv, b0.x, aB[0]); aB[1] = fmaf(xv, b0.y, aB[1]);
        aB[2] = fmaf(xv, b0.z, aB[2]); aB[3] = fmaf(xv, b0.w, aB[3]);
        aB[4] = fmaf(xv, b1.x, aB[4]); aB[5] = fmaf(xv, b1.y, aB[5]);
        aB[6] = fmaf(xv, b1.z, aB[6]); aB[7] = fmaf(xv, b1.w, aB[7]);
        aA[0] = fmaf(xv, a0.x, aA[0]); aA[1] = fmaf(xv, a0.y, aA[1]);
        aA[2] = fmaf(xv, a0.z, aA[2]); aA[3] = fmaf(xv, a0.w, aA[3]);
        aA[4] = fmaf(xv, a1.x, aA[4]); aA[5] = fmaf(xv, a1.y, aA[5]);
        aA[6] = fmaf(xv, a1.z, aA[6]); aA[7] = fmaf(xv, a1.w, aA[7]);
    }
#pragma unroll
    for (int j = 0; j < 8; j++) { aB[j] = warpAllSum(aB[j]); aA[j] = warpAllSum(aA[j]); }
    if (lane == 0) {
#pragma unroll
        for (int j = 0; j < 8; j++) { red2[warp][j] = aB[j]; red2[warp][j + 8] = aA[j]; }
    }
    __syncthreads();
    if (tid < 16) {
        float s = 0.0f;
#pragma unroll
        for (int w8 = 0; w8 < 8; w8++) s += red2[w8][tid];
        if (tid < 8) {
            beta[(size_t)row * CH + tid] = 1.0f / (1.0f + expf(-s));
        } else {
            int j = tid - 8;
            float z = s + dt_bias[j];
            float sp = (z > 20.0f) ? z : log1pf(expf(z));
            float gg = -expf(A_log[j]) * sp;
            eg[(size_t)row * CH + j] = expf(gg);
        }
    }
}

// -------------------- elementwise kernels --------------------------------
__global__ void resid_rms_k(const float* __restrict__ x, const float* __restrict__ a,
                            const float* __restrict__ w, float* __restrict__ x1,
                            __nv_bfloat16* __restrict__ h2h, __nv_bfloat16* __restrict__ h2l) {
    int row = blockIdx.x, tid = threadIdx.x;
    float4 xv = ((const float4*)(x + (size_t)row * CD))[tid];
    float4 av = ((const float4*)(a + (size_t)row * CD))[tid];
    float4 v;
    v.x = xv.x + RES_SCALE * av.x; v.y = xv.y + RES_SCALE * av.y;
    v.z = xv.z + RES_SCALE * av.z; v.w = xv.w + RES_SCALE * av.w;
    ((float4*)(x1 + (size_t)row * CD))[tid] = v;
    float ss = v.x * v.x + v.y * v.y + v.z * v.z + v.w * v.w;
    __shared__ float red[8];
    int lane = tid & 31, warp = tid >> 5;
    ss = warpAllSum(ss);
    if (lane == 0) red[warp] = ss;
    __syncthreads();
    float tot = red[0] + red[1] + red[2] + red[3] + red[4] + red[5] + red[6] + red[7];
    float sc = rsqrtf(tot * (1.0f / CD) + 1e-6f);
    float4 wv = ((const float4*)w)[tid];
    float4 o;
    o.x = v.x * wv.x * sc; o.y = v.y * wv.y * sc;
    o.z = v.z * wv.z * sc; o.w = v.w * wv.w * sc;
    size_t e = (size_t)row * CD + tid * 4;
    split_pair(o.x, o.y, h2h + e, h2l + e);
    split_pair(o.z, o.w, h2h + e + 2, h2l + e + 2);
}

__global__ void onorm_gate_k(const float* __restrict__ o, const float* __restrict__ gate,
                             const float* __restrict__ onw,
                             __nv_bfloat16* __restrict__ oh, __nv_bfloat16* __restrict__ ol) {
    int row = blockIdx.x;
    int lane = threadIdx.x & 31, warp = threadIdx.x >> 5;
    size_t base4 = (size_t)row * (CD / 4) + warp * (CHD / 4) + lane;
    float4 ov = ((const float4*)o)[base4];
    float ss = warpAllSum(ov.x * ov.x + ov.y * ov.y + ov.z * ov.z + ov.w * ov.w);
    float sc = rsqrtf(ss * (1.0f / CHD) + 1e-6f);
    float4 gv = ((const float4*)gate)[base4];
    gv.x = siluf(gv.x); gv.y = siluf(gv.y); gv.z = siluf(gv.z); gv.w = siluf(gv.w);
    float4 wv = ((const float4*)onw)[lane];
    float4 r;
    r.x = ov.x * sc * wv.x * gv.x;
    r.y = ov.y * sc * wv.y * gv.y;
    r.z = ov.z * sc * wv.z * gv.z;
    r.w = ov.w * sc * wv.w * gv.w;
    size_t e = base4 * 4;
    split_pair(r.x, r.y, oh + e, ol + e);
    split_pair(r.z, r.w, oh + e + 2, ol + e + 2);
}

// ------- gated delta-rule scan: depth-8 pipeline, 1 barrier/step ----------
#define SC_ST 8
#define SROW 144
__global__ __launch_bounds__(128) void scan_k(
    const float* __restrict__ q, const float* __restrict__ k,
    const float* __restrict__ v, const float* __restrict__ beta,
    const float* __restrict__ eg, float* __restrict__ o, float* __restrict__ sf) {
    __shared__ float sk[SC_ST][SROW];
    __shared__ float sq[SC_ST][SROW];
    __shared__ float sv[SC_ST][40];

    int bh = blockIdx.x >> 2, quar = blockIdx.x & 3;
    int b = bh >> 3, hh = bh & 7;
    int tid = threadIdx.x;
    int warp = tid >> 5, lane = tid & 31;
    int colL = lane >> 2;
    int col = quar * 32 + warp * 8 + colL;
    int seg = lane & 3;
    int vbase = quar * 32;

    unsigned skb = (unsigned)__cvta_generic_to_shared(sk);
    unsigned sqb = (unsigned)__cvta_generic_to_shared(sq);
    unsigned svb = (unsigned)__cvta_generic_to_shared(sv);

    int rowbase = b * CT * CH + hh;

    auto issue = [&](int t) {
        if (t < CT) {
            int idx = rowbase + t * CH;
            int st = t & (SC_ST - 1);
            if (tid < 32) {
                int d = tid * 4;
                unsigned pos = (unsigned)((st * SROW + (d >> 5) * 36 + (d & 31)) * 4);
                cpa16(skb + pos, k + (size_t)idx * CHD + d);
            } else if (tid < 64) {
                int d = (tid - 32) * 4;
                unsigned pos = (unsigned)((st * SROW + (d >> 5) * 36 + (d & 31)) * 4);
                cpa16(sqb + pos, q + (size_t)idx * CHD + d);
            } else if (tid < 72) {
                int d = (tid - 64) * 4;
                cpa16(svb + (unsigned)((st * 40 + d) * 4), v + (size_t)idx * CHD + vbase + d);
            } else if (tid == 72) {
                cpa4(svb + (unsigned)((st * 40 + 32) * 4), eg + idx);
            } else if (tid == 73) {
                cpa4(svb + (unsigned)((st * 40 + 33) * 4), beta + idx);
            }
        }
        asm volatile("cp.async.commit_group;" ::: "memory");
    };

#pragma unroll
    for (int t = 0; t < SC_ST - 1; t++) issue(t);

    float S[32];
#pragma unroll
    for (int j = 0; j < 32; j++) S[j] = 0.0f;

    for (int t = 0; t < CT; t++) {
        int st = t & (SC_ST - 1);
        asm volatile("cp.async.wait_group 6;" ::: "memory");
        __syncthreads();
        issue(t + SC_ST - 1);
        const float* kp = &sk[st][seg * 36];
        const float* qp = &sq[st][seg * 36];
        float egv = sv[st][32];
        float btv = sv[st][33];
        float vtv = sv[st][warp * 8 + colL];

        float kr[32];
        float kS0 = 0.0f, kS1 = 0.0f, kS2 = 0.0f, kS3 = 0.0f;
#pragma unroll
        for (int j = 0; j < 32; j += 4) {
            float k0 = kp[j], k1 = kp[j + 1], k2 = kp[j + 2], k3 = kp[j + 3];
            kr[j] = k0; kr[j + 1] = k1; kr[j + 2] = k2; kr[j + 3] = k3;
            float s0 = S[j] * egv, s1 = S[j + 1] * egv;
            float s2 = S[j + 2] * egv, s3 = S[j + 3] * egv;
            S[j] = s0; S[j + 1] = s1; S[j + 2] = s2; S[j + 3] = s3;
            kS0 = fmaf(k0, s0, kS0); kS1 = fmaf(k1, s1, kS1);
            kS2 = fmaf(k2, s2, kS2); kS3 = fmaf(k3, s3, kS3);
        }
        float kS = (kS0 + kS1) + (kS2 + kS3);
        kS += __shfl_xor_sync(0xffffffffu, kS, 1);
        kS += __shfl_xor_sync(0xffffffffu, kS, 2);
        float bd = btv * (vtv - kS);

        float o0 = 0.0f, o1 = 0.0f, o2 = 0.0f, o3 = 0.0f;
#pragma unroll
        for (int j = 0; j < 32; j += 4) {
            float s0 = fmaf(kr[j], bd, S[j]);
            float s1 = fmaf(kr[j + 1], bd, S[j + 1]);
            float s2 = fmaf(kr[j + 2], bd, S[j + 2]);
            float s3 = fmaf(kr[j + 3], bd, S[j + 3]);
            S[j] = s0; S[j + 1] = s1; S[j + 2] = s2; S[j + 3] = s3;
            o0 = fmaf(qp[j], s0, o0); o1 = fmaf(qp[j + 1], s1, o1);
            o2 = fmaf(qp[j + 2], s2, o2); o3 = fmaf(qp[j + 3], s3, o3);
        }
        float ot = (o0 + o1) + (o2 + o3);
        ot += __shfl_xor_sync(0xffffffffu, ot, 1);
        ot += __shfl_xor_sync(0xffffffffu, ot, 2);
        if (seg == 0) o[(size_t)(rowbase + t * CH) * CHD + col] = ot;
    }

    float* sfp = sf + ((size_t)bh * CHD + seg * 32) * CHD + col;
#pragma unroll
    for (int j = 0; j < 32; j++) sfp[(size_t)j * CHD] = S[j];
}

// -------------------- launcher --------------------------------------------
static float* symaddrf(const void* sym) {
    void* p = nullptr;
    cudaGetSymbolAddress(&p, sym);
    return (float*)p;
}
static __nv_bfloat16* symaddrb(const void* sym) {
    void* p = nullptr;
    cudaGetSymbolAddress(&p, sym);
    return (__nv_bfloat16*)p;
}

extern "C" void kernel_launch(void* const* d_in, const int* in_sizes, int n_in,
                              void* d_out, int out_size) {
    const float* x       = (const float*)d_in[0];
    const float* ln1_w   = (const float*)d_in[1];
    const float* qw      = (const float*)d_in[2];
    const float* kw      = (const float*)d_in[3];
    const float* vw      = (const float*)d_in[4];
    const float* bw      = (const float*)d_in[5];
    const float* aw      = (const float*)d_in[6];
    const float* A_log   = (const float*)d_in[7];
    const float* dt_bias = (const float*)d_in[8];
    const float* gw      = (const float*)d_in[9];
    const float* onorm_w = (const float*)d_in[10];
    const float* ow      = (const float*)d_in[11];
    const float* ln2_w   = (const float*)d_in[12];
    const float* fcw     = (const float*)d_in[13];
    const float* pw      = (const float*)d_in[14];
    float* y = (float*)d_out;

    float* q_    = symaddrf(g_q);
    float* k_    = symaddrf(g_k);
    float* v_    = symaddrf(g_v);
    float* gate_ = symaddrf(g_gate);
    float* o_    = symaddrf(g_o);
    float* attn_ = symaddrf(g_attn);
    float* x1_   = symaddrf(g_x1);
    float* beta_ = symaddrf(g_beta);
    float* eg_   = symaddrf(g_eg);
    float* sfd_  = symaddrf(g_sfdummy);

    __nv_bfloat16* hh_   = symaddrb(g_hh);
    __nv_bfloat16* hl_   = symaddrb(g_hl);
    __nv_bfloat16* h2h_  = symaddrb(g_h2h);
    __nv_bfloat16* h2l_  = symaddrb(g_h2l);
    __nv_bfloat16* oh_   = symaddrb(g_oh);
    __nv_bfloat16* ol_   = symaddrb(g_ol);
    __nv_bfloat16* mlph_ = symaddrb(g_mlph);
    __nv_bfloat16* mlpl_ = symaddrb(g_mlpl);
    __nv_bfloat16* wth_  = symaddrb(g_wth);
    __nv_bfloat16* wtl_  = symaddrb(g_wtl);

    float* sfdst = (out_size >= YTOT + STOT) ? (y + YTOT) : sfd_;

    static cudaStream_t s2 = nullptr;
    static cudaEvent_t evA = nullptr, evB = nullptr;
    static int smem_set = 0;
    if (!smem_set) {
        cudaFuncSetAttribute(gemm_tc<0>, cudaFuncAttributeMaxDynamicSharedMemorySize, GSMEM);
        cudaFuncSetAttribute(gemm_tc<1>, cudaFuncAttributeMaxDynamicSharedMemorySize, GSMEM);
        cudaFuncSetAttribute(gemm_tc<2>, cudaFuncAttributeMaxDynamicSharedMemorySize, GSMEM);
        cudaFuncSetAttribute(gemm_tc<3>, cudaFuncAttributeMaxDynamicSharedMemorySize, GSMEM);
        cudaFuncSetAttribute(gemm_tc<4>, cudaFuncAttributeMaxDynamicSharedMemorySize, GSMEM);
        cudaStreamCreateWithFlags(&s2, cudaStreamNonBlocking);
        cudaEventCreateWithFlags(&evA, cudaEventDisableTiming);
        cudaEventCreateWithFlags(&evB, cudaEventDisableTiming);
        smem_set = 1;
    }

    dim3 blk(256);
    dim3 g1024(1024 / 128, CM / 128);
    dim3 g4096(4096 / 128, CM / 128);

    rmsnorm_bg_k<<<CM, blk>>>(x, ln1_w, bw, aw, A_log, dt_bias, hh_, hl_, beta_, eg_);
    wsplit_all<<<13312, blk>>>(qw, kw, vw, gw, ow, fcw, pw, wth_, wtl_);
    gemm_tc<2><<<g1024, blk, GSMEM>>>(hh_, hl_, wth_ + W_QW, wtl_ + W_QW, q_, nullptr, nullptr, nullptr, CM, CD, CD);
    gemm_tc<2><<<g1024, blk, GSMEM>>>(hh_, hl_, wth_ + W_KW, wtl_ + W_KW, k_, nullptr, nullptr, nullptr, CM, CD, CD);
    gemm_tc<3><<<g1024, blk, GSMEM>>>(hh_, hl_, wth_ + W_VW, wtl_ + W_VW, v_, nullptr, nullptr, nullptr, CM, CD, CD);

    // fork: scan on side stream, gate GEMM concurrently on main stream
    cudaEventRecord(evA, 0);
    cudaStreamWaitEvent(s2, evA, 0);
    scan_k<<<128, 128, 0, s2>>>(q_, k_, v_, beta_, eg_, o_, sfdst);
    cudaEventRecord(evB, s2);

    gemm_tc<0><<<g1024, blk, GSMEM>>>(hh_, hl_, wth_ + W_GW, wtl_ + W_GW, gate_, nullptr, nullptr, nullptr, CM, CD, CD);

    // join: onorm needs scan output + gate
    cudaStreamWaitEvent(0, evB, 0);
    onorm_gate_k<<<CM, blk>>>(o_, gate_, onorm_w, oh_, ol_);
    gemm_tc<0><<<g1024, blk, GSMEM>>>(oh_, ol_, wth_ + W_OW, wtl_ + W_OW, attn_, nullptr, nullptr, nullptr, CM, CD, CD);
    resid_rms_k<<<CM, blk>>>(x, attn_, ln2_w, x1_, h2h_, h2l_);

    gemm_tc<1><<<g4096, blk, GSMEM>>>(h2h_, h2l_, wth_ + W_FCW, wtl_ + W_FCW, nullptr, mlph_, mlpl_, nullptr, CM, 4 * CD, CD);
    gemm_tc<4><<<g1024, blk, GSMEM>>>(mlph_, mlpl_, wth_ + W_PW, wtl_ + W_PW, y, nullptr, nullptr, x1_, CM, CD, 4 * CD);
}